// round 9
// baseline (speedup 1.0000x reference)
#include <cuda_runtime.h>
#include <cuda_bf16.h>
#include <cuda_fp16.h>
#include <cstdint>

// ---------------------------------------------------------------------------
// RSAGE_Hetero round 8:
//  - task GROUPS share one A tile across multiple weight matrices (xp tile
//    used for 3 outputs, xa for 2, hp1 for 2, ha1 for 1)
//  - weights pre-split to bf16 hi/lo in K1; GEMM fetches W via cp.async with
//    double buffering (prefetch W_{j+1} during pass j's mma)
//  - graph CTAs (hist+scan+fill) still fused into K2; 5 launches
// ---------------------------------------------------------------------------

constexpr int NPn  = 50000;
constexpr int NAn  = 20000;
constexpr int DIN  = 128;
constexpr int DH   = 128;
constexpr int DOUT = 64;
constexpr int EWn  = 250000;
constexpr int ECn  = 500000;
constexpr int ERn  = 250000;
constexpr int NT   = 2 * NPn + NAn;      // 120000 unified node slots
constexpr int ET   = EWn + ECn + ERn;    // 1,000,000
constexpr int GC   = 144;                // graph CTAs (wave-1 resident)

// pre-split weight segments (bf16 hi/lo), 128 elems per row
constexpr int OFF_W1P  = 0;              // 0.5*Wl1[1]   [128x128]
constexpr int OFF_W1R  = 16384;          //     Wl1[2]   [128x128]
constexpr int OFF_WC1  = 32768;          // 0.5*(Wr1[0]+Wr1[1])
constexpr int OFF_W1A  = 49152;          // 0.5*Wl1[0]
constexpr int OFF_WR1A = 65536;          //     Wr1[2]
constexpr int OFF_W2P  = 81920;          // 0.5*Wl2[1]   [64x128]
constexpr int OFF_WC2  = 90112;          // 0.5*(Wr2[0]+Wr2[1])
constexpr int OFF_W2A  = 98304;          // 0.5*Wl2[0]
constexpr int WTOT     = 106496;

// ------------------------------ scratch ------------------------------------
__device__ __half g_yah[NAn * DH];
__device__ __half g_yph[NPn * DH];
__device__ __half g_yrh[NPn * DH];
__device__ __half g_zah[NAn * DOUT];
__device__ __half g_zph[NPn * DOUT];
__device__ float  g_S1p[NPn * DH];
__device__ float  g_S1a[NAn * DH];
__device__ float  g_S2 [NPn * DOUT];
__device__ __nv_bfloat16 g_hp1h[NPn * DH], g_hp1l[NPn * DH];
__device__ __nv_bfloat16 g_ha1h[NAn * DH], g_ha1l[NAn * DH];

__device__ __nv_bfloat16 g_Wh[WTOT], g_Wl[WTOT];
__device__ float g_bc1[DH];
__device__ float g_bc2[DOUT];

__device__ int g_deg[NT], g_off[NT + 1], g_cur[NT], g_src[ET];
__device__ int g_bsum[GC], g_bbase[GC];
__device__ int g_bar[4];

// --------------------------- PTX helpers -----------------------------------
__device__ __forceinline__ uint32_t smem_u32(const void* p) {
    uint32_t a;
    asm("{ .reg .u64 t; cvta.to.shared.u64 t, %1; cvt.u32.u64 %0, t; }"
        : "=r"(a) : "l"(p));
    return a;
}

__device__ __forceinline__ void ldmx4(uint32_t* r, uint32_t addr) {
    asm volatile(
        "ldmatrix.sync.aligned.m8n8.x4.shared.b16 {%0,%1,%2,%3}, [%4];"
        : "=r"(r[0]), "=r"(r[1]), "=r"(r[2]), "=r"(r[3]) : "r"(addr));
}

__device__ __forceinline__ void mma16816(float* c, const uint32_t* a,
                                         uint32_t b0, uint32_t b1) {
    asm volatile(
        "mma.sync.aligned.m16n8k16.row.col.f32.bf16.bf16.f32 "
        "{%0,%1,%2,%3}, {%4,%5,%6,%7}, {%8,%9}, {%0,%1,%2,%3};"
        : "+f"(c[0]), "+f"(c[1]), "+f"(c[2]), "+f"(c[3])
        : "r"(a[0]), "r"(a[1]), "r"(a[2]), "r"(a[3]), "r"(b0), "r"(b1));
}

#define CPASYNC16(dst, src) \
    asm volatile("cp.async.ca.shared.global [%0], [%1], 16;" \
                 :: "r"(dst), "l"(src))
#define CPASYNC_COMMIT()  asm volatile("cp.async.commit_group;" ::: "memory")
#define CPASYNC_WAIT0()   asm volatile("cp.async.wait_group 0;" ::: "memory")

__device__ __forceinline__ void graph_bar(int idx) {
    __syncthreads();
    if (threadIdx.x == 0) {
        __threadfence();
        atomicAdd(&g_bar[idx], 1);
        while (*(volatile int*)&g_bar[idx] < GC) __nanosleep(64);
    }
    __syncthreads();
    __threadfence();
}

// --------------------------- setup: zero + weight pre-split -----------------
__global__ void zero_prep_kernel(const float* __restrict__ Wl1,
                                 const float* __restrict__ bl1,
                                 const float* __restrict__ Wr1,
                                 const float* __restrict__ Wl2,
                                 const float* __restrict__ bl2,
                                 const float* __restrict__ Wr2) {
    int i = blockIdx.x * blockDim.x + threadIdx.x;
    if (i < NT) g_deg[i] = 0;
    if (i < 4)  g_bar[i] = 0;
    if (i == 0) g_off[NT] = ET;
    if (i < DH)   g_bc1[i] = 0.5f * (bl1[i] + bl1[DH + i]);
    if (i < DOUT) g_bc2[i] = 0.5f * (bl2[i] + bl2[DOUT + i]);

    if (i < WTOT) {
        float v;
        if (i < OFF_W1R)       v = 0.5f * Wl1[16384 + i];
        else if (i < OFF_WC1)  v = Wl1[32768 + (i - OFF_W1R)];
        else if (i < OFF_W1A)  { int j = i - OFF_WC1; v = 0.5f * (Wr1[j] + Wr1[16384 + j]); }
        else if (i < OFF_WR1A) v = 0.5f * Wl1[i - OFF_W1A];
        else if (i < OFF_W2P)  v = Wr1[32768 + (i - OFF_WR1A)];
        else if (i < OFF_WC2)  v = 0.5f * Wl2[8192 + (i - OFF_W2P)];
        else if (i < OFF_W2A)  { int j = i - OFF_WC2; v = 0.5f * (Wr2[j] + Wr2[8192 + j]); }
        else                   v = 0.5f * Wl2[i - OFF_W2A];
        __nv_bfloat16 hi = __float2bfloat16(v);
        g_Wh[i] = hi;
        g_Wl[i] = __float2bfloat16(v - __bfloat162float(hi));
    }
}

// --------------------------- graph CTA program -------------------------------
__device__ void graph_cta(int c, char* smemRaw,
                          const int* wsrc, const int* wdst,
                          const int* csrc, const int* cdst,
                          const int* rsrc, const int* rdst) {
    int* s = (int*)smemRaw;
    const int tid = threadIdx.x;
    const int tg = c * 512 + tid;
    const int stride = GC * 512;

    for (int i = tg; i < EWn / 4; i += stride) {
        int4 d = ((const int4*)wdst)[i];
        atomicAdd(&g_deg[d.x], 1); atomicAdd(&g_deg[d.y], 1);
        atomicAdd(&g_deg[d.z], 1); atomicAdd(&g_deg[d.w], 1);
    }
    for (int i = tg; i < ECn / 4; i += stride) {
        int4 d = ((const int4*)cdst)[i];
        atomicAdd(&g_deg[NPn + d.x], 1); atomicAdd(&g_deg[NPn + d.y], 1);
        atomicAdd(&g_deg[NPn + d.z], 1); atomicAdd(&g_deg[NPn + d.w], 1);
    }
    for (int i = tg; i < ERn / 4; i += stride) {
        int4 d = ((const int4*)rdst)[i];
        atomicAdd(&g_deg[2 * NPn + d.x], 1); atomicAdd(&g_deg[2 * NPn + d.y], 1);
        atomicAdd(&g_deg[2 * NPn + d.z], 1); atomicAdd(&g_deg[2 * NPn + d.w], 1);
    }
    graph_bar(0);

    const int i0 = c * 1024 + tid * 2;
    const int e0 = (i0 < NT) ? g_deg[i0] : 0;
    const int e1 = (i0 + 1 < NT) ? g_deg[i0 + 1] : 0;
    const int tsum = e0 + e1;
    s[tid] = tsum;
    __syncthreads();
    #pragma unroll
    for (int d = 1; d < 512; d <<= 1) {
        int v = (tid >= d) ? s[tid - d] : 0;
        __syncthreads();
        s[tid] += v;
        __syncthreads();
    }
    const int pre = s[tid] - tsum;
    if (tid == 511) g_bsum[c] = s[511];
    graph_bar(1);

    if (c == 0) {
        int v = (tid < GC) ? g_bsum[tid] : 0;
        s[tid] = v;
        __syncthreads();
        #pragma unroll
        for (int d = 1; d < 512; d <<= 1) {
            int t = (tid >= d) ? s[tid - d] : 0;
            __syncthreads();
            s[tid] += t;
            __syncthreads();
        }
        if (tid < GC) g_bbase[tid] = s[tid] - v;
    }
    graph_bar(2);

    {
        const int base = g_bbase[c] + pre;
        if (i0 < NT)     { g_off[i0] = base;          g_cur[i0] = base; }
        if (i0 + 1 < NT) { g_off[i0 + 1] = base + e0; g_cur[i0 + 1] = base + e0; }
    }
    graph_bar(3);

    for (int i = tg; i < EWn / 4; i += stride) {
        int4 d = ((const int4*)wdst)[i];
        int4 sv = ((const int4*)wsrc)[i];
        g_src[atomicAdd(&g_cur[d.x], 1)] = sv.x;
        g_src[atomicAdd(&g_cur[d.y], 1)] = sv.y;
        g_src[atomicAdd(&g_cur[d.z], 1)] = sv.z;
        g_src[atomicAdd(&g_cur[d.w], 1)] = sv.w;
    }
    for (int i = tg; i < ECn / 4; i += stride) {
        int4 d = ((const int4*)cdst)[i];
        int4 sv = ((const int4*)csrc)[i];
        g_src[atomicAdd(&g_cur[NPn + d.x], 1)] = sv.x;
        g_src[atomicAdd(&g_cur[NPn + d.y], 1)] = sv.y;
        g_src[atomicAdd(&g_cur[NPn + d.z], 1)] = sv.z;
        g_src[atomicAdd(&g_cur[NPn + d.w], 1)] = sv.w;
    }
    for (int i = tg; i < ERn / 4; i += stride) {
        int4 d = ((const int4*)rdst)[i];
        int4 sv = ((const int4*)rsrc)[i];
        g_src[atomicAdd(&g_cur[2 * NPn + d.x], 1)] = sv.x;
        g_src[atomicAdd(&g_cur[2 * NPn + d.y], 1)] = sv.y;
        g_src[atomicAdd(&g_cur[2 * NPn + d.z], 1)] = sv.z;
        g_src[atomicAdd(&g_cur[2 * NPn + d.w], 1)] = sv.w;
    }
}

// ---------------------- grouped multi-pass GEMM ------------------------------
// For one 128-row A block: npass outputs C_j = A @ W_j^T (+bias_j), W_j
// pre-split bf16 (alpha folded). 3-term split per pass. cp.async W pipeline.
struct MTask {
    const void* A;         // fp32 rows, or bf16 hi rows if Alo != null
    const void* Alo;       // bf16 lo rows
    int woff[3];           // offsets into g_Wh/g_Wl
    void* C[3];
    const float* bias[3];  // nullable
    int outHalf[3];
    int M;
    int npass;
    int ctaEnd;            // absolute
};

template <int BN>
__global__ void __launch_bounds__(512, 1)
tc_mega(MTask t0, MTask t1, int gc,
        const int* wsrc, const int* wdst, const int* csrc, const int* cdst,
        const int* rsrc, const int* rdst) {
    constexpr int LDS = 136;
    constexpr int MT  = (BN == 128) ? 2 : 1;
    constexpr int MW  = (BN == 128) ? 4 : 8;
    constexpr int NT_ = 4;
    constexpr int WBUF = 2 * BN * LDS;     // bf16 elems per W buffer (hi+lo)

    extern __shared__ __align__(16) char smemRaw[];
    const int bId = blockIdx.x;

    if (bId < gc) {
        graph_cta(bId, smemRaw, wsrc, wdst, csrc, cdst, rsrc, rdst);
        return;
    }

    MTask t;
    int base;
    if (bId < t0.ctaEnd) { t = t0; base = gc; }
    else                 { t = t1; base = t0.ctaEnd; }

    __nv_bfloat16* sm  = (__nv_bfloat16*)smemRaw;
    __nv_bfloat16* sAhi = sm;
    __nv_bfloat16* sAlo = sAhi + 128 * LDS;
    __nv_bfloat16* sWb  = sAlo + 128 * LDS;    // two buffers of WBUF each

    const int tid  = threadIdx.x;
    const int lane = tid & 31;
    const int wid  = tid >> 5;
    const int m0   = (bId - base) * 128;
    const int M    = t.M;
    const int cg   = (tid & 15) * 8;

    // ---- prefetch W pass 0 (cp.async) ----
    {
        const uint32_t wb = smem_u32(sWb);
        const __nv_bfloat16* gh = g_Wh + t.woff[0];
        const __nv_bfloat16* gl = g_Wl + t.woff[0];
        #pragma unroll
        for (int r = tid >> 4; r < BN; r += 32) {
            CPASYNC16(wb + (uint32_t)(r * LDS + cg) * 2, gh + r * 128 + cg);
            CPASYNC16(wb + (uint32_t)((BN + r) * LDS + cg) * 2, gl + r * 128 + cg);
        }
        CPASYNC_COMMIT();
    }

    // ---- A tiles ----
    if (t.Alo) {
        const __nv_bfloat16* Ah = (const __nv_bfloat16*)t.A;
        const __nv_bfloat16* Al = (const __nv_bfloat16*)t.Alo;
        #pragma unroll
        for (int r = tid >> 4; r < 128; r += 32) {
            const int gm = m0 + r;
            uint4 vh = make_uint4(0, 0, 0, 0), vl = vh;
            if (gm < M) {
                vh = *(const uint4*)(Ah + (size_t)gm * 128 + cg);
                vl = *(const uint4*)(Al + (size_t)gm * 128 + cg);
            }
            *(uint4*)(sAhi + r * LDS + cg) = vh;
            *(uint4*)(sAlo + r * LDS + cg) = vl;
        }
    } else {
        const float* A = (const float*)t.A;
        #pragma unroll
        for (int r = tid >> 4; r < 128; r += 32) {
            const int gm = m0 + r;
            float4 v0 = make_float4(0.f, 0.f, 0.f, 0.f), v1 = v0;
            if (gm < M) {
                const float4* p = (const float4*)(A + (size_t)gm * 128 + cg);
                v0 = p[0];
                v1 = p[1];
            }
            float f[8] = {v0.x, v0.y, v0.z, v0.w, v1.x, v1.y, v1.z, v1.w};
            __nv_bfloat16 hi[8], lo[8];
            #pragma unroll
            for (int i = 0; i < 8; i++) {
                hi[i] = __float2bfloat16(f[i]);
                lo[i] = __float2bfloat16(f[i] - __bfloat162float(hi[i]));
            }
            *(uint4*)(sAhi + r * LDS + cg) = *(uint4*)hi;
            *(uint4*)(sAlo + r * LDS + cg) = *(uint4*)lo;
        }
    }
    CPASYNC_WAIT0();
    __syncthreads();

    const uint32_t aAhi = smem_u32(sAhi);
    const uint32_t aAlo = smem_u32(sAlo);
    const uint32_t aWb  = smem_u32(sWb);

    const int wm = (wid % MW) * (MT * 16);
    const int wn = (wid / MW) * 32;
    const int arow  = lane & 15;
    const int acol8 = (lane >> 4) * 8;
    const int brow  = (lane & 7) + ((lane >> 4) << 3);
    const int bcol8 = ((lane >> 3) & 1) * 8;

    for (int j = 0; j < t.npass; j++) {
        // prefetch next W into alternate buffer
        if (j + 1 < t.npass) {
            const uint32_t wb = aWb + (uint32_t)(((j + 1) & 1) * WBUF) * 2;
            const __nv_bfloat16* gh = g_Wh + t.woff[j + 1];
            const __nv_bfloat16* gl = g_Wl + t.woff[j + 1];
            #pragma unroll
            for (int r = tid >> 4; r < BN; r += 32) {
                CPASYNC16(wb + (uint32_t)(r * LDS + cg) * 2, gh + r * 128 + cg);
                CPASYNC16(wb + (uint32_t)((BN + r) * LDS + cg) * 2, gl + r * 128 + cg);
            }
            CPASYNC_COMMIT();
        }

        const uint32_t wHi = aWb + (uint32_t)((j & 1) * WBUF) * 2;
        const uint32_t wLo = wHi + (uint32_t)(BN * LDS) * 2;

        float acc[MT][NT_][4];
        #pragma unroll
        for (int mt = 0; mt < MT; mt++)
            #pragma unroll
            for (int nt = 0; nt < NT_; nt++)
                #pragma unroll
                for (int q = 0; q < 4; q++) acc[mt][nt][q] = 0.f;

        #pragma unroll
        for (int k = 0; k < 8; k++) {
            const int kc = k * 16;
            uint32_t ahi[MT][4], alo[MT][4];
            #pragma unroll
            for (int mt = 0; mt < MT; mt++) {
                const uint32_t off =
                    (uint32_t)((wm + mt * 16 + arow) * LDS + kc + acol8) * 2;
                ldmx4(ahi[mt], aAhi + off);
                ldmx4(alo[mt], aAlo + off);
            }
            #pragma unroll
            for (int np = 0; np < NT_ / 2; np++) {
                const uint32_t boff =
                    (uint32_t)((wn + np * 16 + brow) * LDS + kc + bcol8) * 2;
                uint32_t bhi[4], blo[4];
                ldmx4(bhi, wHi + boff);
                ldmx4(blo, wLo + boff);
                #pragma unroll
                for (int mt = 0; mt < MT; mt++) {
                    #pragma unroll
                    for (int h = 0; h < 2; h++) {
                        float* c = acc[mt][np * 2 + h];
                        mma16816(c, ahi[mt], bhi[2 * h], bhi[2 * h + 1]);
                        mma16816(c, alo[mt], bhi[2 * h], bhi[2 * h + 1]);
                        mma16816(c, ahi[mt], blo[2 * h], blo[2 * h + 1]);
                    }
                }
            }
        }

        // epilogue for pass j
        const float* bias = t.bias[j];
        const int oh = t.outHalf[j];
        #pragma unroll
        for (int mt = 0; mt < MT; mt++) {
            const int r0 = m0 + wm + mt * 16 + (lane >> 2);
            #pragma unroll
            for (int nt = 0; nt < NT_; nt++) {
                const int col = wn + nt * 8 + (lane & 3) * 2;
                const float* c = acc[mt][nt];
                #pragma unroll
                for (int h = 0; h < 2; h++) {
                    const int gm = r0 + h * 8;
                    if (gm < M) {
                        float vx = c[2 * h], vy = c[2 * h + 1];
                        if (bias) { vx += bias[col]; vy += bias[col + 1]; }
                        if (oh) {
                            *(__half2*)((__half*)t.C[j] + (size_t)gm * BN + col) =
                                __floats2half2_rn(vx, vy);
                        } else {
                            *(float2*)((float*)t.C[j] + (size_t)gm * BN + col) =
                                make_float2(vx, vy);
                        }
                    }
                }
            }
        }

        if (j + 1 < t.npass) {
            CPASYNC_WAIT0();
            __syncthreads();
        }
    }
}

// ------------------------------ gathers -------------------------------------
__device__ __forceinline__ void acc_rel128(int b, int e, int lane,
                                           const __half* __restrict__ y,
                                           float* res) {
    float acc[4] = {0.f, 0.f, 0.f, 0.f};
    int i = b;
    for (; i + 3 < e; i += 4) {
        #pragma unroll
        for (int k = 0; k < 4; k++) {
            const int s = __ldg(&g_src[i + k]);
            uint2 u = *(const uint2*)(y + (size_t)s * 128 + lane * 4);
            float2 a0 = __half22float2(*(const __half2*)&u.x);
            float2 a1 = __half22float2(*(const __half2*)&u.y);
            acc[0] += a0.x; acc[1] += a0.y; acc[2] += a1.x; acc[3] += a1.y;
        }
    }
    for (; i < e; i++) {
        const int s = __ldg(&g_src[i]);
        uint2 u = *(const uint2*)(y + (size_t)s * 128 + lane * 4);
        float2 a0 = __half22float2(*(const __half2*)&u.x);
        float2 a1 = __half22float2(*(const __half2*)&u.y);
        acc[0] += a0.x; acc[1] += a0.y; acc[2] += a1.x; acc[3] += a1.y;
    }
    const int deg = e - b;
    const float inv = deg > 0 ? 1.f / (float)deg : 0.f;
    #pragma unroll
    for (int v = 0; v < 4; v++) res[v] += acc[v] * inv;
}

__global__ void gather_l1_kernel() {
    const int gw   = (blockIdx.x * blockDim.x + threadIdx.x) >> 5;
    const int lane = threadIdx.x & 31;
    float res[4] = {0.f, 0.f, 0.f, 0.f};
    const float* S;
    __nv_bfloat16 *oh, *ol;
    int node;
    if (gw < NPn) {
        node = gw;
        acc_rel128(g_off[gw], g_off[gw + 1], lane, g_yah, res);
        acc_rel128(g_off[NPn + gw], g_off[NPn + gw + 1], lane, g_yph, res);
        S = g_S1p; oh = g_hp1h; ol = g_hp1l;
    } else if (gw < NPn + NAn) {
        node = gw - NPn;
        acc_rel128(g_off[2 * NPn + node], g_off[2 * NPn + node + 1], lane, g_yrh, res);
        S = g_S1a; oh = g_ha1h; ol = g_ha1l;
    } else {
        return;
    }
    float4 s4 = *(const float4*)(S + (size_t)node * 128 + lane * 4);
    float v[4] = {fmaxf(s4.x + res[0], 0.f), fmaxf(s4.y + res[1], 0.f),
                  fmaxf(s4.z + res[2], 0.f), fmaxf(s4.w + res[3], 0.f)};
    __nv_bfloat16 hi[4], lo[4];
    #pragma unroll
    for (int k = 0; k < 4; k++) {
        hi[k] = __float2bfloat16(v[k]);
        lo[k] = __float2bfloat16(v[k] - __bfloat162float(hi[k]));
    }
    *(uint2*)(oh + (size_t)node * 128 + lane * 4) = *(uint2*)hi;
    *(uint2*)(ol + (size_t)node * 128 + lane * 4) = *(uint2*)lo;
}

__global__ void gather_l2_kernel(float* __restrict__ out) {
    const int gw   = (blockIdx.x * blockDim.x + threadIdx.x) >> 5;
    const int lane = threadIdx.x & 31;
    if (gw >= NPn) return;

    float res[2] = {0.f, 0.f};
    #pragma unroll
    for (int rel = 0; rel < 2; rel++) {
        const __half* y = rel ? g_zph : g_zah;
        const int b = g_off[rel * NPn + gw];
        const int e = g_off[rel * NPn + gw + 1];
        float acc0 = 0.f, acc1 = 0.f;
        int i = b;
        for (; i + 3 < e; i += 4) {
            #pragma unroll
            for (int k = 0; k < 4; k++) {
                const int s = __ldg(&g_src[i + k]);
                float2 a = __half22float2(*(const __half2*)(y + (size_t)s * 64 + lane * 2));
                acc0 += a.x; acc1 += a.y;
            }
        }
        for (; i < e; i++) {
            const int s = __ldg(&g_src[i]);
            float2 a = __half22float2(*(const __half2*)(y + (size_t)s * 64 + lane * 2));
            acc0 += a.x; acc1 += a.y;
        }
        const int deg = e - b;
        const float inv = deg > 0 ? 1.f / (float)deg : 0.f;
        res[0] += acc0 * inv;
        res[1] += acc1 * inv;
    }
    float2 s2 = *(const float2*)(g_S2 + (size_t)gw * 64 + lane * 2);
    *(float2*)(out + (size_t)gw * 64 + lane * 2) =
        make_float2(s2.x + res[0], s2.y + res[1]);
}

// ------------------------------- launch -------------------------------------
extern "C" void kernel_launch(void* const* d_in, const int* in_sizes, int n_in,
                              void* d_out, int out_size) {
    const float* xp  = (const float*)d_in[0];
    const float* xa  = (const float*)d_in[1];
    const float* Wl1 = (const float*)d_in[2];
    const float* bl1 = (const float*)d_in[3];
    const float* Wr1 = (const float*)d_in[4];
    const float* Wl2 = (const float*)d_in[5];
    const float* bl2 = (const float*)d_in[6];
    const float* Wr2 = (const float*)d_in[7];
    const int* wsrc = (const int*)d_in[8];
    const int* wdst = (const int*)d_in[9];
    const int* csrc = (const int*)d_in[10];
    const int* cdst = (const int*)d_in[11];
    const int* rsrc = (const int*)d_in[12];
    const int* rdst = (const int*)d_in[13];
    float* out = (float*)d_out;

    __half *p_yah, *p_yph, *p_yrh, *p_zah, *p_zph;
    float *p_S1p, *p_S1a, *p_S2, *p_bc1, *p_bc2;
    __nv_bfloat16 *p_hp1h, *p_hp1l, *p_ha1h, *p_ha1l;
    cudaGetSymbolAddress((void**)&p_yah, g_yah);
    cudaGetSymbolAddress((void**)&p_yph, g_yph);
    cudaGetSymbolAddress((void**)&p_yrh, g_yrh);
    cudaGetSymbolAddress((void**)&p_zah, g_zah);
    cudaGetSymbolAddress((void**)&p_zph, g_zph);
    cudaGetSymbolAddress((void**)&p_S1p, g_S1p);
    cudaGetSymbolAddress((void**)&p_S1a, g_S1a);
    cudaGetSymbolAddress((void**)&p_S2,  g_S2);
    cudaGetSymbolAddress((void**)&p_bc1, g_bc1);
    cudaGetSymbolAddress((void**)&p_bc2, g_bc2);
    cudaGetSymbolAddress((void**)&p_hp1h, g_hp1h);
    cudaGetSymbolAddress((void**)&p_hp1l, g_hp1l);
    cudaGetSymbolAddress((void**)&p_ha1h, g_ha1h);
    cudaGetSymbolAddress((void**)&p_ha1l, g_ha1l);

    // smem: A(2*128*136*2) + 2 W buffers (2 * 2*BN*136*2)
    constexpr int SMEM128 = 2 * 128 * 136 * 2 + 2 * (2 * 128 * 136 * 2); // 208896
    constexpr int SMEM64  = 2 * 128 * 136 * 2 + 2 * (2 * 64 * 136 * 2);  // 139264
    cudaFuncSetAttribute((const void*)tc_mega<128>,
                         cudaFuncAttributeMaxDynamicSharedMemorySize, SMEM128);
    cudaFuncSetAttribute((const void*)tc_mega<64>,
                         cudaFuncAttributeMaxDynamicSharedMemorySize, SMEM64);

    const int gNP = (NPn + 127) / 128;   // 391
    const int gNA = (NAn + 127) / 128;   // 157

    // K1: zero + pre-split weights + biases
    zero_prep_kernel<<<(NT + 255) / 256, 256>>>(Wl1, bl1, Wr1, Wl2, bl2, Wr2);

    // K2: graph CTAs + L1 grouped GEMMs
    {
        MTask tx = {};   // xp group: yph, yrh, S1p
        tx.A = xp; tx.Alo = nullptr;
        tx.woff[0] = OFF_W1P;  tx.C[0] = p_yph; tx.bias[0] = nullptr; tx.outHalf[0] = 1;
        tx.woff[1] = OFF_W1R;  tx.C[1] = p_yrh; tx.bias[1] = nullptr; tx.outHalf[1] = 1;
        tx.woff[2] = OFF_WC1;  tx.C[2] = p_S1p; tx.bias[2] = p_bc1;   tx.outHalf[2] = 0;
        tx.M = NPn; tx.npass = 3; tx.ctaEnd = GC + gNP;

        MTask ty = {};   // xa group: yah, S1a
        ty.A = xa; ty.Alo = nullptr;
        ty.woff[0] = OFF_W1A;  ty.C[0] = p_yah; ty.bias[0] = nullptr;      ty.outHalf[0] = 1;
        ty.woff[1] = OFF_WR1A; ty.C[1] = p_S1a; ty.bias[1] = bl1 + 2 * DH; ty.outHalf[1] = 0;
        ty.woff[2] = OFF_WR1A; ty.C[2] = p_S1a; ty.bias[2] = nullptr;      ty.outHalf[2] = 0;
        ty.M = NAn; ty.npass = 2; ty.ctaEnd = GC + gNP + gNA;

        tc_mega<128><<<GC + gNP + gNA, 512, SMEM128>>>(
            tx, ty, GC, wsrc, wdst, csrc, cdst, rsrc, rdst);
    }

    // K3: L1 gather + relu + bf16-pair split
    gather_l1_kernel<<<((NPn + NAn) * 32) / 256, 256>>>();

    // K4: L2 grouped GEMMs (hp1 group: zph, S2 | ha1 group: zah)
    {
        MTask tp = {};
        tp.A = p_hp1h; tp.Alo = p_hp1l;
        tp.woff[0] = OFF_W2P; tp.C[0] = p_zph; tp.bias[0] = nullptr; tp.outHalf[0] = 1;
        tp.woff[1] = OFF_WC2; tp.C[1] = p_S2;  tp.bias[1] = p_bc2;   tp.outHalf[1] = 0;
        tp.woff[2] = OFF_WC2; tp.C[2] = p_S2;  tp.bias[2] = nullptr; tp.outHalf[2] = 0;
        tp.M = NPn; tp.npass = 2; tp.ctaEnd = gNP;

        MTask ta = {};
        ta.A = p_ha1h; ta.Alo = p_ha1l;
        ta.woff[0] = OFF_W2A; ta.C[0] = p_zah; ta.bias[0] = nullptr; ta.outHalf[0] = 1;
        ta.woff[1] = OFF_W2A; ta.C[1] = p_zah; ta.bias[1] = nullptr; ta.outHalf[1] = 1;
        ta.woff[2] = OFF_W2A; ta.C[2] = p_zah; ta.bias[2] = nullptr; ta.outHalf[2] = 1;
        ta.M = NAn; ta.npass = 1; ta.ctaEnd = gNP + gNA;

        tc_mega<64><<<gNP + gNA, 512, SMEM64>>>(
            tp, ta, 0, nullptr, nullptr, nullptr, nullptr, nullptr, nullptr);
    }

    // K5: L2 gather -> d_out
    gather_l2_kernel<<<(NPn * 32) / 256, 256>>>(out);
}

// round 10
// speedup vs baseline: 1.1494x; 1.1494x over previous
#include <cuda_runtime.h>
#include <cuda_bf16.h>
#include <cuda_fp16.h>
#include <cstdint>

// ---------------------------------------------------------------------------
// RSAGE_Hetero round 9:
//  - REVERT R8 grouping (regressed; latency-bound regime wants parallelism)
//  - BM=64 tiles + 256-thread CTAs -> 2-3 CTAs/SM (occupancy fix)
//  - weights pre-split to bf16 hi/lo in K1 (W smem fill = pure copy)
//  - graph CTAs (hist+scan+fill) fused into K2 with 256-thread layout
//  - 5 launches
// ---------------------------------------------------------------------------

constexpr int NPn  = 50000;
constexpr int NAn  = 20000;
constexpr int DIN  = 128;
constexpr int DH   = 128;
constexpr int DOUT = 64;
constexpr int EWn  = 250000;
constexpr int ECn  = 500000;
constexpr int ERn  = 250000;
constexpr int NT   = 2 * NPn + NAn;      // 120000
constexpr int ET   = EWn + ECn + ERn;    // 1,000,000
constexpr int GC   = 144;                // graph CTAs

// pre-split weight segments (bf16 hi/lo), 128 elems per row, alpha folded
constexpr int OFF_W1P  = 0;              // 0.5*Wl1[1]   [128x128]
constexpr int OFF_W1R  = 16384;          //     Wl1[2]   [128x128]
constexpr int OFF_WC1  = 32768;          // 0.5*(Wr1[0]+Wr1[1])
constexpr int OFF_W1A  = 49152;          // 0.5*Wl1[0]
constexpr int OFF_WR1A = 65536;          //     Wr1[2]
constexpr int OFF_W2P  = 81920;          // 0.5*Wl2[1]   [64x128]
constexpr int OFF_WC2  = 90112;          // 0.5*(Wr2[0]+Wr2[1])
constexpr int OFF_W2A  = 98304;          // 0.5*Wl2[0]
constexpr int WTOT     = 106496;

// ------------------------------ scratch ------------------------------------
__device__ __half g_yah[NAn * DH];
__device__ __half g_yph[NPn * DH];
__device__ __half g_yrh[NPn * DH];
__device__ __half g_zah[NAn * DOUT];
__device__ __half g_zph[NPn * DOUT];
__device__ float  g_S1p[NPn * DH];
__device__ float  g_S1a[NAn * DH];
__device__ float  g_S2 [NPn * DOUT];
__device__ __nv_bfloat16 g_hp1h[NPn * DH], g_hp1l[NPn * DH];
__device__ __nv_bfloat16 g_ha1h[NAn * DH], g_ha1l[NAn * DH];

__device__ __nv_bfloat16 g_Wh[WTOT], g_Wl[WTOT];
__device__ float g_bc1[DH];
__device__ float g_bc2[DOUT];

__device__ int g_deg[NT], g_off[NT + 1], g_cur[NT], g_src[ET];
__device__ int g_bsum[GC], g_bbase[GC];
__device__ int g_bar[4];

// --------------------------- PTX helpers -----------------------------------
__device__ __forceinline__ uint32_t smem_u32(const void* p) {
    uint32_t a;
    asm("{ .reg .u64 t; cvta.to.shared.u64 t, %1; cvt.u32.u64 %0, t; }"
        : "=r"(a) : "l"(p));
    return a;
}

__device__ __forceinline__ void ldmx4(uint32_t* r, uint32_t addr) {
    asm volatile(
        "ldmatrix.sync.aligned.m8n8.x4.shared.b16 {%0,%1,%2,%3}, [%4];"
        : "=r"(r[0]), "=r"(r[1]), "=r"(r[2]), "=r"(r[3]) : "r"(addr));
}

__device__ __forceinline__ void mma16816(float* c, const uint32_t* a,
                                         uint32_t b0, uint32_t b1) {
    asm volatile(
        "mma.sync.aligned.m16n8k16.row.col.f32.bf16.bf16.f32 "
        "{%0,%1,%2,%3}, {%4,%5,%6,%7}, {%8,%9}, {%0,%1,%2,%3};"
        : "+f"(c[0]), "+f"(c[1]), "+f"(c[2]), "+f"(c[3])
        : "r"(a[0]), "r"(a[1]), "r"(a[2]), "r"(a[3]), "r"(b0), "r"(b1));
}

__device__ __forceinline__ void graph_bar(int idx) {
    __syncthreads();
    if (threadIdx.x == 0) {
        __threadfence();
        atomicAdd(&g_bar[idx], 1);
        while (*(volatile int*)&g_bar[idx] < GC) __nanosleep(64);
    }
    __syncthreads();
    __threadfence();
}

// --------------------------- setup: zero + weight pre-split -----------------
__global__ void zero_prep_kernel(const float* __restrict__ Wl1,
                                 const float* __restrict__ bl1,
                                 const float* __restrict__ Wr1,
                                 const float* __restrict__ Wl2,
                                 const float* __restrict__ bl2,
                                 const float* __restrict__ Wr2) {
    int i = blockIdx.x * blockDim.x + threadIdx.x;
    if (i < NT) g_deg[i] = 0;
    if (i < 4)  g_bar[i] = 0;
    if (i == 0) g_off[NT] = ET;
    if (i < DH)   g_bc1[i] = 0.5f * (bl1[i] + bl1[DH + i]);
    if (i < DOUT) g_bc2[i] = 0.5f * (bl2[i] + bl2[DOUT + i]);

    if (i < WTOT) {
        float v;
        if (i < OFF_W1R)       v = 0.5f * Wl1[16384 + i];
        else if (i < OFF_WC1)  v = Wl1[32768 + (i - OFF_W1R)];
        else if (i < OFF_W1A)  { int j = i - OFF_WC1; v = 0.5f * (Wr1[j] + Wr1[16384 + j]); }
        else if (i < OFF_WR1A) v = 0.5f * Wl1[i - OFF_W1A];
        else if (i < OFF_W2P)  v = Wr1[32768 + (i - OFF_WR1A)];
        else if (i < OFF_WC2)  v = 0.5f * Wl2[8192 + (i - OFF_W2P)];
        else if (i < OFF_W2A)  { int j = i - OFF_WC2; v = 0.5f * (Wr2[j] + Wr2[8192 + j]); }
        else                   v = 0.5f * Wl2[i - OFF_W2A];
        __nv_bfloat16 hi = __float2bfloat16(v);
        g_Wh[i] = hi;
        g_Wl[i] = __float2bfloat16(v - __bfloat162float(hi));
    }
}

// --------------------------- graph CTA program (256 threads) ----------------
__device__ void graph_cta(int c, char* smemRaw,
                          const int* wsrc, const int* wdst,
                          const int* csrc, const int* cdst,
                          const int* rsrc, const int* rdst) {
    int* s = (int*)smemRaw;                    // 256 ints
    const int tid = threadIdx.x;
    const int tg = c * 256 + tid;
    const int stride = GC * 256;

    // ---- phase A: histogram ----
    for (int i = tg; i < EWn / 4; i += stride) {
        int4 d = ((const int4*)wdst)[i];
        atomicAdd(&g_deg[d.x], 1); atomicAdd(&g_deg[d.y], 1);
        atomicAdd(&g_deg[d.z], 1); atomicAdd(&g_deg[d.w], 1);
    }
    for (int i = tg; i < ECn / 4; i += stride) {
        int4 d = ((const int4*)cdst)[i];
        atomicAdd(&g_deg[NPn + d.x], 1); atomicAdd(&g_deg[NPn + d.y], 1);
        atomicAdd(&g_deg[NPn + d.z], 1); atomicAdd(&g_deg[NPn + d.w], 1);
    }
    for (int i = tg; i < ERn / 4; i += stride) {
        int4 d = ((const int4*)rdst)[i];
        atomicAdd(&g_deg[2 * NPn + d.x], 1); atomicAdd(&g_deg[2 * NPn + d.y], 1);
        atomicAdd(&g_deg[2 * NPn + d.z], 1); atomicAdd(&g_deg[2 * NPn + d.w], 1);
    }
    graph_bar(0);

    // ---- phase B1: per-CTA chunk scan (1024 deg entries, 4 per thread) ----
    const int i0 = c * 1024 + tid * 4;
    int e[4];
    int tsum = 0;
    #pragma unroll
    for (int k = 0; k < 4; k++) {
        e[k] = (i0 + k < NT) ? g_deg[i0 + k] : 0;
        tsum += e[k];
    }
    s[tid] = tsum;
    __syncthreads();
    #pragma unroll
    for (int d = 1; d < 256; d <<= 1) {
        int v = (tid >= d) ? s[tid - d] : 0;
        __syncthreads();
        s[tid] += v;
        __syncthreads();
    }
    const int pre = s[tid] - tsum;
    if (tid == 255) g_bsum[c] = s[255];
    graph_bar(1);

    // ---- phase B2: CTA 0 scans block sums ----
    if (c == 0) {
        int v = (tid < GC) ? g_bsum[tid] : 0;
        s[tid] = v;
        __syncthreads();
        #pragma unroll
        for (int d = 1; d < 256; d <<= 1) {
            int t = (tid >= d) ? s[tid - d] : 0;
            __syncthreads();
            s[tid] += t;
            __syncthreads();
        }
        if (tid < GC) g_bbase[tid] = s[tid] - v;
    }
    graph_bar(2);

    // ---- phase B3: write offsets ----
    {
        int run = g_bbase[c] + pre;
        #pragma unroll
        for (int k = 0; k < 4; k++) {
            if (i0 + k < NT) {
                g_off[i0 + k] = run;
                g_cur[i0 + k] = run;
                run += e[k];
            }
        }
    }
    graph_bar(3);

    // ---- phase C: fill ----
    for (int i = tg; i < EWn / 4; i += stride) {
        int4 d = ((const int4*)wdst)[i];
        int4 sv = ((const int4*)wsrc)[i];
        g_src[atomicAdd(&g_cur[d.x], 1)] = sv.x;
        g_src[atomicAdd(&g_cur[d.y], 1)] = sv.y;
        g_src[atomicAdd(&g_cur[d.z], 1)] = sv.z;
        g_src[atomicAdd(&g_cur[d.w], 1)] = sv.w;
    }
    for (int i = tg; i < ECn / 4; i += stride) {
        int4 d = ((const int4*)cdst)[i];
        int4 sv = ((const int4*)csrc)[i];
        g_src[atomicAdd(&g_cur[NPn + d.x], 1)] = sv.x;
        g_src[atomicAdd(&g_cur[NPn + d.y], 1)] = sv.y;
        g_src[atomicAdd(&g_cur[NPn + d.z], 1)] = sv.z;
        g_src[atomicAdd(&g_cur[NPn + d.w], 1)] = sv.w;
    }
    for (int i = tg; i < ERn / 4; i += stride) {
        int4 d = ((const int4*)rdst)[i];
        int4 sv = ((const int4*)rsrc)[i];
        g_src[atomicAdd(&g_cur[2 * NPn + d.x], 1)] = sv.x;
        g_src[atomicAdd(&g_cur[2 * NPn + d.y], 1)] = sv.y;
        g_src[atomicAdd(&g_cur[2 * NPn + d.z], 1)] = sv.z;
        g_src[atomicAdd(&g_cur[2 * NPn + d.w], 1)] = sv.w;
    }
}

// ---------------------- flat per-task GEMM, BM=64, 256 threads ---------------
struct GTask {
    const void* A;         // fp32 rows, or bf16 hi rows if Alo != null
    const void* Alo;       // bf16 lo rows
    int woff;              // offset into g_Wh/g_Wl (pre-split, alpha folded)
    void* C;
    const float* bias;     // nullable
    int M;
    int ctaEnd;            // absolute
    int outHalf;
};

// C[M,BN] = A[M,128] @ W[BN,128]^T (+bias); 3-term split, fp32 accum.
template <int BN>
__global__ void __launch_bounds__(256, 2)
tc_mega(GTask t0, GTask t1, GTask t2, GTask t3, GTask t4, int gc,
        const int* wsrc, const int* wdst, const int* csrc, const int* cdst,
        const int* rsrc, const int* rdst) {
    constexpr int LDS = 136;
    constexpr int BM  = 64;
    constexpr int MT  = (BN == 128) ? 2 : 1;   // m16 tiles per warp
    constexpr int MW  = (BN == 128) ? 2 : 4;   // warps along m
    constexpr int NT_ = 4;                     // n8 tiles per warp (32 cols)

    extern __shared__ __align__(16) char smemRaw[];
    const int bId = blockIdx.x;

    if (bId < gc) {
        graph_cta(bId, smemRaw, wsrc, wdst, csrc, cdst, rsrc, rdst);
        return;
    }

    GTask t;
    int base;
    if (bId < t0.ctaEnd)      { t = t0; base = gc; }
    else if (bId < t1.ctaEnd) { t = t1; base = t0.ctaEnd; }
    else if (bId < t2.ctaEnd) { t = t2; base = t1.ctaEnd; }
    else if (bId < t3.ctaEnd) { t = t3; base = t2.ctaEnd; }
    else                      { t = t4; base = t3.ctaEnd; }

    __nv_bfloat16* sm  = (__nv_bfloat16*)smemRaw;
    __nv_bfloat16* sAhi = sm;
    __nv_bfloat16* sAlo = sAhi + BM * LDS;
    __nv_bfloat16* sWhi = sAlo + BM * LDS;
    __nv_bfloat16* sWlo = sWhi + BN * LDS;

    const int tid  = threadIdx.x;
    const int lane = tid & 31;
    const int wid  = tid >> 5;
    const int m0   = (bId - base) * BM;
    const int M    = t.M;
    const int cg   = (tid & 15) * 8;

    // ---- A tile (64 rows) ----
    if (t.Alo) {
        const __nv_bfloat16* Ah = (const __nv_bfloat16*)t.A;
        const __nv_bfloat16* Al = (const __nv_bfloat16*)t.Alo;
        #pragma unroll
        for (int r = tid >> 4; r < BM; r += 16) {
            const int gm = m0 + r;
            uint4 vh = make_uint4(0, 0, 0, 0), vl = vh;
            if (gm < M) {
                vh = *(const uint4*)(Ah + (size_t)gm * 128 + cg);
                vl = *(const uint4*)(Al + (size_t)gm * 128 + cg);
            }
            *(uint4*)(sAhi + r * LDS + cg) = vh;
            *(uint4*)(sAlo + r * LDS + cg) = vl;
        }
    } else {
        const float* A = (const float*)t.A;
        #pragma unroll
        for (int r = tid >> 4; r < BM; r += 16) {
            const int gm = m0 + r;
            float4 v0 = make_float4(0.f, 0.f, 0.f, 0.f), v1 = v0;
            if (gm < M) {
                const float4* p = (const float4*)(A + (size_t)gm * 128 + cg);
                v0 = p[0];
                v1 = p[1];
            }
            float f[8] = {v0.x, v0.y, v0.z, v0.w, v1.x, v1.y, v1.z, v1.w};
            __nv_bfloat16 hi[8], lo[8];
            #pragma unroll
            for (int i = 0; i < 8; i++) {
                hi[i] = __float2bfloat16(f[i]);
                lo[i] = __float2bfloat16(f[i] - __bfloat162float(hi[i]));
            }
            *(uint4*)(sAhi + r * LDS + cg) = *(uint4*)hi;
            *(uint4*)(sAlo + r * LDS + cg) = *(uint4*)lo;
        }
    }
    // ---- W tiles (pre-split: pure copy) ----
    {
        const __nv_bfloat16* gh = g_Wh + t.woff;
        const __nv_bfloat16* gl = g_Wl + t.woff;
        #pragma unroll
        for (int r = tid >> 4; r < BN; r += 16) {
            *(uint4*)(sWhi + r * LDS + cg) = *(const uint4*)(gh + r * 128 + cg);
            *(uint4*)(sWlo + r * LDS + cg) = *(const uint4*)(gl + r * 128 + cg);
        }
    }
    __syncthreads();

    // ---- warp-tiled mma mainloop ----
    const int wm = (wid % MW) * (MT * 16);
    const int wn = (wid / MW) * 32;

    float acc[MT][NT_][4];
    #pragma unroll
    for (int mt = 0; mt < MT; mt++)
        #pragma unroll
        for (int nt = 0; nt < NT_; nt++)
            #pragma unroll
            for (int j = 0; j < 4; j++) acc[mt][nt][j] = 0.f;

    const uint32_t aAhi = smem_u32(sAhi);
    const uint32_t aAlo = smem_u32(sAlo);
    const uint32_t aWhi = smem_u32(sWhi);
    const uint32_t aWlo = smem_u32(sWlo);

    const int arow  = lane & 15;
    const int acol8 = (lane >> 4) * 8;
    const int brow  = (lane & 7) + ((lane >> 4) << 3);
    const int bcol8 = ((lane >> 3) & 1) * 8;

    #pragma unroll
    for (int k = 0; k < 8; k++) {
        const int kc = k * 16;
        uint32_t ahi[MT][4], alo[MT][4];
        #pragma unroll
        for (int mt = 0; mt < MT; mt++) {
            const uint32_t off =
                (uint32_t)((wm + mt * 16 + arow) * LDS + kc + acol8) * 2;
            ldmx4(ahi[mt], aAhi + off);
            ldmx4(alo[mt], aAlo + off);
        }
        #pragma unroll
        for (int np = 0; np < NT_ / 2; np++) {
            const uint32_t boff =
                (uint32_t)((wn + np * 16 + brow) * LDS + kc + bcol8) * 2;
            uint32_t bhi[4], blo[4];
            ldmx4(bhi, aWhi + boff);
            ldmx4(blo, aWlo + boff);
            #pragma unroll
            for (int mt = 0; mt < MT; mt++) {
                #pragma unroll
                for (int h = 0; h < 2; h++) {
                    float* c = acc[mt][np * 2 + h];
                    mma16816(c, ahi[mt], bhi[2 * h], bhi[2 * h + 1]);
                    mma16816(c, alo[mt], bhi[2 * h], bhi[2 * h + 1]);
                    mma16816(c, ahi[mt], blo[2 * h], blo[2 * h + 1]);
                }
            }
        }
    }

    // ---- epilogue ----
    #pragma unroll
    for (int mt = 0; mt < MT; mt++) {
        const int r0 = m0 + wm + mt * 16 + (lane >> 2);
        #pragma unroll
        for (int nt = 0; nt < NT_; nt++) {
            const int col = wn + nt * 8 + (lane & 3) * 2;
            const float* c = acc[mt][nt];
            #pragma unroll
            for (int h = 0; h < 2; h++) {
                const int gm = r0 + h * 8;
                if (gm < M) {
                    float vx = c[2 * h], vy = c[2 * h + 1];
                    if (t.bias) { vx += t.bias[col]; vy += t.bias[col + 1]; }
                    if (t.outHalf) {
                        *(__half2*)((__half*)t.C + (size_t)gm * BN + col) =
                            __floats2half2_rn(vx, vy);
                    } else {
                        *(float2*)((float*)t.C + (size_t)gm * BN + col) =
                            make_float2(vx, vy);
                    }
                }
            }
        }
    }
}

// ------------------------------ gathers -------------------------------------
__device__ __forceinline__ void acc_rel128(int b, int e, int lane,
                                           const __half* __restrict__ y,
                                           float* res) {
    float acc[4] = {0.f, 0.f, 0.f, 0.f};
    int i = b;
    for (; i + 3 < e; i += 4) {
        #pragma unroll
        for (int k = 0; k < 4; k++) {
            const int s = __ldg(&g_src[i + k]);
            uint2 u = *(const uint2*)(y + (size_t)s * 128 + lane * 4);
            float2 a0 = __half22float2(*(const __half2*)&u.x);
            float2 a1 = __half22float2(*(const __half2*)&u.y);
            acc[0] += a0.x; acc[1] += a0.y; acc[2] += a1.x; acc[3] += a1.y;
        }
    }
    for (; i < e; i++) {
        const int s = __ldg(&g_src[i]);
        uint2 u = *(const uint2*)(y + (size_t)s * 128 + lane * 4);
        float2 a0 = __half22float2(*(const __half2*)&u.x);
        float2 a1 = __half22float2(*(const __half2*)&u.y);
        acc[0] += a0.x; acc[1] += a0.y; acc[2] += a1.x; acc[3] += a1.y;
    }
    const int deg = e - b;
    const float inv = deg > 0 ? 1.f / (float)deg : 0.f;
    #pragma unroll
    for (int v = 0; v < 4; v++) res[v] += acc[v] * inv;
}

__global__ void gather_l1_kernel() {
    const int gw   = (blockIdx.x * blockDim.x + threadIdx.x) >> 5;
    const int lane = threadIdx.x & 31;
    float res[4] = {0.f, 0.f, 0.f, 0.f};
    const float* S;
    __nv_bfloat16 *oh, *ol;
    int node;
    if (gw < NPn) {
        node = gw;
        acc_rel128(g_off[gw], g_off[gw + 1], lane, g_yah, res);
        acc_rel128(g_off[NPn + gw], g_off[NPn + gw + 1], lane, g_yph, res);
        S = g_S1p; oh = g_hp1h; ol = g_hp1l;
    } else if (gw < NPn + NAn) {
        node = gw - NPn;
        acc_rel128(g_off[2 * NPn + node], g_off[2 * NPn + node + 1], lane, g_yrh, res);
        S = g_S1a; oh = g_ha1h; ol = g_ha1l;
    } else {
        return;
    }
    float4 s4 = *(const float4*)(S + (size_t)node * 128 + lane * 4);
    float v[4] = {fmaxf(s4.x + res[0], 0.f), fmaxf(s4.y + res[1], 0.f),
                  fmaxf(s4.z + res[2], 0.f), fmaxf(s4.w + res[3], 0.f)};
    __nv_bfloat16 hi[4], lo[4];
    #pragma unroll
    for (int k = 0; k < 4; k++) {
        hi[k] = __float2bfloat16(v[k]);
        lo[k] = __float2bfloat16(v[k] - __bfloat162float(hi[k]));
    }
    *(uint2*)(oh + (size_t)node * 128 + lane * 4) = *(uint2*)hi;
    *(uint2*)(ol + (size_t)node * 128 + lane * 4) = *(uint2*)lo;
}

__global__ void gather_l2_kernel(float* __restrict__ out) {
    const int gw   = (blockIdx.x * blockDim.x + threadIdx.x) >> 5;
    const int lane = threadIdx.x & 31;
    if (gw >= NPn) return;

    float res[2] = {0.f, 0.f};
    #pragma unroll
    for (int rel = 0; rel < 2; rel++) {
        const __half* y = rel ? g_zph : g_zah;
        const int b = g_off[rel * NPn + gw];
        const int e = g_off[rel * NPn + gw + 1];
        float acc0 = 0.f, acc1 = 0.f;
        int i = b;
        for (; i + 3 < e; i += 4) {
            #pragma unroll
            for (int k = 0; k < 4; k++) {
                const int s = __ldg(&g_src[i + k]);
                float2 a = __half22float2(*(const __half2*)(y + (size_t)s * 64 + lane * 2));
                acc0 += a.x; acc1 += a.y;
            }
        }
        for (; i < e; i++) {
            const int s = __ldg(&g_src[i]);
            float2 a = __half22float2(*(const __half2*)(y + (size_t)s * 64 + lane * 2));
            acc0 += a.x; acc1 += a.y;
        }
        const int deg = e - b;
        const float inv = deg > 0 ? 1.f / (float)deg : 0.f;
        res[0] += acc0 * inv;
        res[1] += acc1 * inv;
    }
    float2 s2 = *(const float2*)(g_S2 + (size_t)gw * 64 + lane * 2);
    *(float2*)(out + (size_t)gw * 64 + lane * 2) =
        make_float2(s2.x + res[0], s2.y + res[1]);
}

// ------------------------------- launch -------------------------------------
extern "C" void kernel_launch(void* const* d_in, const int* in_sizes, int n_in,
                              void* d_out, int out_size) {
    const float* xp  = (const float*)d_in[0];
    const float* xa  = (const float*)d_in[1];
    const float* Wl1 = (const float*)d_in[2];
    const float* bl1 = (const float*)d_in[3];
    const float* Wr1 = (const float*)d_in[4];
    const float* Wl2 = (const float*)d_in[5];
    const float* bl2 = (const float*)d_in[6];
    const float* Wr2 = (const float*)d_in[7];
    const int* wsrc = (const int*)d_in[8];
    const int* wdst = (const int*)d_in[9];
    const int* csrc = (const int*)d_in[10];
    const int* cdst = (const int*)d_in[11];
    const int* rsrc = (const int*)d_in[12];
    const int* rdst = (const int*)d_in[13];
    float* out = (float*)d_out;

    __half *p_yah, *p_yph, *p_yrh, *p_zah, *p_zph;
    float *p_S1p, *p_S1a, *p_S2, *p_bc1, *p_bc2;
    __nv_bfloat16 *p_hp1h, *p_hp1l, *p_ha1h, *p_ha1l;
    cudaGetSymbolAddress((void**)&p_yah, g_yah);
    cudaGetSymbolAddress((void**)&p_yph, g_yph);
    cudaGetSymbolAddress((void**)&p_yrh, g_yrh);
    cudaGetSymbolAddress((void**)&p_zah, g_zah);
    cudaGetSymbolAddress((void**)&p_zph, g_zph);
    cudaGetSymbolAddress((void**)&p_S1p, g_S1p);
    cudaGetSymbolAddress((void**)&p_S1a, g_S1a);
    cudaGetSymbolAddress((void**)&p_S2,  g_S2);
    cudaGetSymbolAddress((void**)&p_bc1, g_bc1);
    cudaGetSymbolAddress((void**)&p_bc2, g_bc2);
    cudaGetSymbolAddress((void**)&p_hp1h, g_hp1h);
    cudaGetSymbolAddress((void**)&p_hp1l, g_hp1l);
    cudaGetSymbolAddress((void**)&p_ha1h, g_ha1h);
    cudaGetSymbolAddress((void**)&p_ha1l, g_ha1l);

    // smem: A pair (2*64*136*2) + W pair (2*BN*136*2)
    constexpr int SMEM128 = 2 * 64 * 136 * 2 + 2 * 128 * 136 * 2;  // 104448
    constexpr int SMEM64  = 2 * 64 * 136 * 2 + 2 * 64 * 136 * 2;   //  69632
    cudaFuncSetAttribute((const void*)tc_mega<128>,
                         cudaFuncAttributeMaxDynamicSharedMemorySize, SMEM128);
    cudaFuncSetAttribute((const void*)tc_mega<64>,
                         cudaFuncAttributeMaxDynamicSharedMemorySize, SMEM64);

    const int gNP = (NPn + 63) / 64;   // 782
    const int gNA = (NAn + 63) / 64;   // 313

    // K1: zero + pre-split weights + biases
    zero_prep_kernel<<<(NT + 255) / 256, 256>>>(Wl1, bl1, Wr1, Wl2, bl2, Wr2);

    // K2: graph CTAs + L1 flat GEMMs (yah | yph | yrh | S1p | S1a)
    {
        int e0 = GC + gNA;
        int e1 = e0 + gNP;
        int e2 = e1 + gNP;
        int e3 = e2 + gNP;
        int e4 = e3 + gNA;
        GTask ta = {xa, nullptr, OFF_W1A,  p_yah, nullptr,      NAn, e0, 1};
        GTask tp = {xp, nullptr, OFF_W1P,  p_yph, nullptr,      NPn, e1, 1};
        GTask tr = {xp, nullptr, OFF_W1R,  p_yrh, nullptr,      NPn, e2, 1};
        GTask ts = {xp, nullptr, OFF_WC1,  p_S1p, p_bc1,        NPn, e3, 0};
        GTask tu = {xa, nullptr, OFF_WR1A, p_S1a, bl1 + 2 * DH, NAn, e4, 0};
        tc_mega<128><<<e4, 256, SMEM128>>>(ta, tp, tr, ts, tu, GC,
                                           wsrc, wdst, csrc, cdst, rsrc, rdst);
    }

    // K3: L1 gather + relu + bf16-pair split
    gather_l1_kernel<<<((NPn + NAn) * 32) / 256, 256>>>();

    // K4: L2 flat GEMMs (zah | zph | S2)
    {
        int e0 = gNA;
        int e1 = e0 + gNP;
        int e2 = e1 + gNP;
        GTask ta = {p_ha1h, p_ha1l, OFF_W2A, p_zah, nullptr, NAn, e0, 1};
        GTask tp = {p_hp1h, p_hp1l, OFF_W2P, p_zph, nullptr, NPn, e1, 1};
        GTask ts = {p_hp1h, p_hp1l, OFF_WC2, p_S2,  p_bc2,   NPn, e2, 0};
        tc_mega<64><<<e2, 256, SMEM64>>>(ta, tp, ts, ts, ts, 0,
                                         nullptr, nullptr, nullptr, nullptr,
                                         nullptr, nullptr);
    }

    // K5: L2 gather -> d_out
    gather_l2_kernel<<<(NPn * 32) / 256, 256>>>(out);
}